// round 15
// baseline (speedup 1.0000x reference)
#include <cuda_runtime.h>
#include <cuda_fp16.h>
#include <cstdint>

// ---------------- problem constants ----------------
#define BB 16
#define HH 112
#define WW 112
#define CINC 128
#define FF 256
#define EE 3
#define OH 110
#define OW 110
#define NPIX_IN  (BB * HH * WW)
#define NPIX_OUT (BB * OH * OW)
#define DD 1152
#define CWRD 4
#define NJOBS (128 * OH)                    // 14080 (b,fs,row) jobs
#define NCTA  148

#if defined(__CUDA_ARCH__) && defined(__CUDA_ARCH_FEAT_SM103_ALL)
#define HAS_TCG 1
#else
#define HAS_TCG 0
#endif

// A row buffer in GLOBAL: 112 px x 128 ch fp16, per-pixel SW128-granule layout.
#define RB 28672
// B tile (per dy): 96 n-rows (n = dx*32+f) x 128 ch fp16, blocked SW128,
// cc chunk stride 12288B. 24576B per tile, 3 tiles per filter slice.
#define BT 24576
#define NTHREADS 416                        // 8 epi + 4 loader + 1 mma warps

// TMEM layout: A ring 4 slots x 64 cols at 0..255; D ping-pong 2 x 96 at 256..447
#define TM_A 0
#define TM_D 256

// smem layout (main kernel)
#define SM_TMEM   0
#define SM_BBAR   64
#define SM_BEMPTY 96
#define SM_AFULL(i)  (128 + (i) * 16)
#define SM_AEMPTY(i) (192 + (i) * 16)
#define SM_ACC(p)    (256 + (p) * 16)
#define SM_EPI(p)    (288 + (p) * 16)
#define SMEM_B    1024
#define ST_D1     (SMEM_B + 3 * BT)         // 74752; 4 x 128 floats
#define ST_D2     (ST_D1 + 4 * 128 * 4)     // 76800; 4 x 256 floats
#define SMEM_TOT  (ST_D2 + 4 * 256 * 4 + 64)  // 80960

// popc fallback smem
#define KWORDS (FF * EE * 9 * CWRD)
#define POPC_SMEM ((KWORDS + EE * FF) * 4)

// idesc: kind::f16 fp16 inputs, fp32 accum, M=128, N=96
#define MMA_IDESC ((1u << 4) | ((96 / 8) << 17) | ((128 / 16) << 24))

// ---------------- scratch (device globals) ----------------
__device__ __align__(1024) unsigned char g_xq[(size_t)BB * HH * RB + 32768];
__device__ __align__(1024) unsigned char g_w[(size_t)8 * 3 * BT];
__device__ float    g_S[NPIX_IN];
__device__ float    g_beta[NPIX_OUT];
__device__ unsigned g_xbits[NPIX_IN * CWRD];
__device__ unsigned g_kbits[KWORDS];

// ---------------- generic PTX helpers ----------------
__device__ __forceinline__ uint32_t smem_u32(const void* p) {
    uint32_t a;
    asm("{ .reg .u64 t; cvta.to.shared.u64 t, %1; cvt.u32.u64 %0, t; }" : "=r"(a) : "l"(p));
    return a;
}
__device__ __forceinline__ uint32_t elect_one() {
    uint32_t pred;
    asm volatile("{\n\t.reg .pred p;\n\telect.sync _|p, 0xFFFFFFFF;\n\tselp.b32 %0, 1, 0, p;\n\t}" : "=r"(pred));
    return pred;
}
#define MBARRIER_INIT(a, c) \
    asm volatile("mbarrier.init.shared.b64 [%0], %1;" :: "r"((uint32_t)(a)), "r"((uint32_t)(c)) : "memory")
#define MBARRIER_EXPECT_TX(a, b) \
    asm volatile("mbarrier.arrive.expect_tx.shared.b64 _, [%0], %1;" :: "r"((uint32_t)(a)), "r"((uint32_t)(b)) : "memory")
#define MBARRIER_ARRIVE(a) \
    asm volatile("mbarrier.arrive.shared.b64 _, [%0];" :: "r"((uint32_t)(a)) : "memory")
#define MBARRIER_INVAL(a) \
    asm volatile("mbarrier.inval.shared.b64 [%0];" :: "r"((uint32_t)(a)) : "memory")
#define MBARRIER_WAIT(a, par) do {                                           \
    uint32_t _m = (uint32_t)(a); uint32_t _p = (uint32_t)(par);              \
    asm volatile("{\n\t.reg .pred P1;\n\t"                                   \
        "WAIT_LP_%=:\n\t"                                                    \
        "mbarrier.try_wait.parity.acquire.cta.shared::cta.b64 P1, [%0], %1, 0x989680;\n\t" \
        "@P1 bra.uni WAIT_DN_%=;\n\t"                                        \
        "bra.uni WAIT_LP_%=;\n\t"                                            \
        "WAIT_DN_%=:\n\t}" :: "r"(_m), "r"(_p) : "memory");                  \
} while (0)
#define BULK_G2S(dst, src, bytes, mbar) \
    asm volatile("cp.async.bulk.shared::cluster.global.mbarrier::complete_tx::bytes [%0], [%1], %2, [%3];" \
        :: "r"((uint32_t)(dst)), "l"(src), "r"((uint32_t)(bytes)), "r"((uint32_t)(mbar)) : "memory")

// ---------------- tcgen05 helpers (sm_103a only) ----------------
#if HAS_TCG
#define TCGEN05_ALLOC(sa, n) \
    asm volatile("tcgen05.alloc.cta_group::1.sync.aligned.shared::cta.b32 [%0], %1;" \
        :: "r"((uint32_t)(sa)), "r"((uint32_t)(n)) : "memory")
#define TCGEN05_DEALLOC(t, n) \
    asm volatile("tcgen05.dealloc.cta_group::1.sync.aligned.b32 %0, %1;" :: "r"(t), "r"((uint32_t)(n)))
#define TCGEN05_RELINQ() \
    asm volatile("tcgen05.relinquish_alloc_permit.cta_group::1.sync.aligned;")
#define TCGEN05_COMMIT(mb) \
    asm volatile("tcgen05.commit.cta_group::1.mbarrier::arrive::one.shared::cluster.b64 [%0];" \
        :: "r"((uint32_t)(mb)) : "memory")
#define TCGEN05_FENCE_AFTER()  asm volatile("tcgen05.fence::after_thread_sync;" ::: "memory")
#define TCGEN05_FENCE_BEFORE() asm volatile("tcgen05.fence::before_thread_sync;" ::: "memory")
#define TCGEN05_WAIT_LD()      asm volatile("tcgen05.wait::ld.sync.aligned;" ::: "memory")
#define TCGEN05_WAIT_ST()      asm volatile("tcgen05.wait::st.sync.aligned;" ::: "memory")

#define TCGEN05_LD_X32(r, ta)                                                 \
    asm volatile("tcgen05.ld.sync.aligned.32x32b.x32.b32 "                    \
        "{%0, %1, %2, %3, %4, %5, %6, %7, %8, %9, %10, %11, %12, %13, %14, %15, " \
        " %16, %17, %18, %19, %20, %21, %22, %23, %24, %25, %26, %27, %28, %29, %30, %31}, [%32];" \
        : "=r"((r)[0]), "=r"((r)[1]), "=r"((r)[2]), "=r"((r)[3]),             \
          "=r"((r)[4]), "=r"((r)[5]), "=r"((r)[6]), "=r"((r)[7]),             \
          "=r"((r)[8]), "=r"((r)[9]), "=r"((r)[10]), "=r"((r)[11]),           \
          "=r"((r)[12]), "=r"((r)[13]), "=r"((r)[14]), "=r"((r)[15]),         \
          "=r"((r)[16]), "=r"((r)[17]), "=r"((r)[18]), "=r"((r)[19]),         \
          "=r"((r)[20]), "=r"((r)[21]), "=r"((r)[22]), "=r"((r)[23]),         \
          "=r"((r)[24]), "=r"((r)[25]), "=r"((r)[26]), "=r"((r)[27]),         \
          "=r"((r)[28]), "=r"((r)[29]), "=r"((r)[30]), "=r"((r)[31])          \
        : "r"(ta))

#define TCGEN05_ST_X64(ta, r)                                                 \
    asm volatile("tcgen05.st.sync.aligned.32x32b.x64.b32 [%0], "              \
        "{%1, %2, %3, %4, %5, %6, %7, %8, "                                   \
        " %9, %10, %11, %12, %13, %14, %15, %16, "                            \
        " %17, %18, %19, %20, %21, %22, %23, %24, "                           \
        " %25, %26, %27, %28, %29, %30, %31, %32, "                           \
        " %33, %34, %35, %36, %37, %38, %39, %40, "                           \
        " %41, %42, %43, %44, %45, %46, %47, %48, "                           \
        " %49, %50, %51, %52, %53, %54, %55, %56, "                           \
        " %57, %58, %59, %60, %61, %62, %63, %64};"                           \
        :: "r"(ta),                                                           \
           "r"((r)[0]),  "r"((r)[1]),  "r"((r)[2]),  "r"((r)[3]),             \
           "r"((r)[4]),  "r"((r)[5]),  "r"((r)[6]),  "r"((r)[7]),             \
           "r"((r)[8]),  "r"((r)[9]),  "r"((r)[10]), "r"((r)[11]),            \
           "r"((r)[12]), "r"((r)[13]), "r"((r)[14]), "r"((r)[15]),            \
           "r"((r)[16]), "r"((r)[17]), "r"((r)[18]), "r"((r)[19]),            \
           "r"((r)[20]), "r"((r)[21]), "r"((r)[22]), "r"((r)[23]),            \
           "r"((r)[24]), "r"((r)[25]), "r"((r)[26]), "r"((r)[27]),            \
           "r"((r)[28]), "r"((r)[29]), "r"((r)[30]), "r"((r)[31]),            \
           "r"((r)[32]), "r"((r)[33]), "r"((r)[34]), "r"((r)[35]),            \
           "r"((r)[36]), "r"((r)[37]), "r"((r)[38]), "r"((r)[39]),            \
           "r"((r)[40]), "r"((r)[41]), "r"((r)[42]), "r"((r)[43]),            \
           "r"((r)[44]), "r"((r)[45]), "r"((r)[46]), "r"((r)[47]),            \
           "r"((r)[48]), "r"((r)[49]), "r"((r)[50]), "r"((r)[51]),            \
           "r"((r)[52]), "r"((r)[53]), "r"((r)[54]), "r"((r)[55]),            \
           "r"((r)[56]), "r"((r)[57]), "r"((r)[58]), "r"((r)[59]),            \
           "r"((r)[60]), "r"((r)[61]), "r"((r)[62]), "r"((r)[63])             \
        : "memory")

// TS-form f16 MMA: A in TMEM, B via SMEM descriptor (test_mma.cu pattern).
__device__ __forceinline__ void mma_f16_ts(uint32_t d, uint32_t a_tmem, uint64_t bdesc,
                                           uint32_t idesc, uint32_t en) {
    asm volatile(
        "{\n\t.reg .pred p;\n\tsetp.ne.u32 p, %5, 0;\n\t"
        "tcgen05.mma.cta_group::1.kind::f16 [%0], [%1], %2, %3, {%4, %4, %4, %4}, p;\n\t}"
        :: "r"(d), "r"(a_tmem), "l"(bdesc), "r"(idesc), "r"(0u), "r"(en) : "memory");
}

// SW128 K-major descriptor, 1024-aligned bases only (B operand).
__device__ __forceinline__ uint64_t make_desc(uint32_t addr) {
    return (uint64_t(2) << 61) | (uint64_t(1) << 46) | (uint64_t(64) << 32) | (uint64_t(1) << 16)
         | ((uint64_t)((addr >> 4) & 0x3FFF));
}
#endif  // HAS_TCG

// ---------------------------------------------------------------------------
// Prep 1: binarize x; one warp per input pixel. Always computes g_S.
// ---------------------------------------------------------------------------
__global__ __launch_bounds__(256) void binarize_kernel(const float* __restrict__ x) {
    int warp = (blockIdx.x * 256 + threadIdx.x) >> 5;
    int lane = threadIdx.x & 31;
    if (warp >= NPIX_IN) return;

    const float4 v = reinterpret_cast<const float4*>(x + (size_t)warp * CINC)[lane];
    float s = fabsf(v.x) + fabsf(v.y) + fabsf(v.z) + fabsf(v.w);
    #pragma unroll
    for (int off = 16; off > 0; off >>= 1) s += __shfl_xor_sync(0xFFFFFFFFu, s, off);
    if (lane == 0) g_S[warp] = s;

#if HAS_TCG
    unsigned h01 = (v.x >= 0.f ? 0x3C00u : 0xBC00u) | ((v.y >= 0.f ? 0x3C00u : 0xBC00u) << 16);
    unsigned h23 = (v.z >= 0.f ? 0x3C00u : 0xBC00u) | ((v.w >= 0.f ? 0x3C00u : 0xBC00u) << 16);
    int w  = warp % WW;
    int ro = warp / WW;
    int c  = lane * 4;
    unsigned o = (unsigned)(c >> 6) * 14336 + (unsigned)w * 128 + (c & 63) * 2;
    unsigned swz = o ^ ((o >> 3) & 0x70);
    *reinterpret_cast<uint2*>(g_xq + (size_t)ro * RB + swz) = make_uint2(h01, h23);
#else
    unsigned nib = (v.x >= 0.f ? 1u : 0u) | (v.y >= 0.f ? 2u : 0u)
                 | (v.z >= 0.f ? 4u : 0u) | (v.w >= 0.f ? 8u : 0u);
    unsigned wv = nib << (4 * (lane & 7));
    wv |= __shfl_xor_sync(0xFFFFFFFFu, wv, 1);
    wv |= __shfl_xor_sync(0xFFFFFFFFu, wv, 2);
    wv |= __shfl_xor_sync(0xFFFFFFFFu, wv, 4);
    if ((lane & 7) == 0) g_xbits[warp * CWRD + (lane >> 3)] = wv;
#endif
}

// ---------------------------------------------------------------------------
// Prep 2a (sm_103a): Wc[tap,c,f] = sum_e alpha[e,f]*sign(K[e,tap,c,f]), fp16.
// Per filter-slice fs: 3 tiles (dy); tile rows n = dx*32 + (f&31), 128 ch,
// blocked SW128 (cc chunk stride 12288B).
// ---------------------------------------------------------------------------
__global__ __launch_bounds__(256) void wpack_kernel(const float* __restrict__ k,
                                                    const float* __restrict__ alphas) {
#if HAS_TCG
    int tid = blockIdx.x * 256 + threadIdx.x;
    if (tid >= 9 * CINC * FF) return;
    int f = tid & 255;
    int c = (tid >> 8) & 127;
    int tap = tid >> 15;              // 0..8, = dy*3+dx
    int dy = tap / 3, dx = tap % 3;

    float wc = 0.f;
    #pragma unroll
    for (int e = 0; e < EE; e++) {
        float kv = k[(((size_t)e * 9 + tap) * CINC + c) * FF + f];
        float a  = alphas[e * FF + f];
        wc += (kv >= 0.f) ? a : -a;
    }
    int fs = f >> 5;
    int n  = dx * 32 + (f & 31);      // row within N=96 tile
    unsigned o = (unsigned)(c >> 6) * 12288 + (unsigned)n * 128 + (c & 63) * 2;
    unsigned swz = o ^ ((o >> 3) & 0x70);
    *reinterpret_cast<unsigned short*>(g_w + (size_t)(fs * 3 + dy) * BT + swz) =
        __half_as_ushort(__float2half_rn(wc));
#endif
}

// Prep 2b (fallback): packed kernel sign bits.
__global__ __launch_bounds__(256) void kpack_kernel(const float* __restrict__ k) {
#if !HAS_TCG
    int idx  = (blockIdx.x * blockDim.x + threadIdx.x) >> 5;
    int lane = threadIdx.x & 31;
    if (idx >= KWORDS) return;
    int w   = idx & (CWRD - 1);
    int t3  = idx >> 2;
    int tap = t3 % 9;
    int fe  = t3 / 9;
    int e   = fe % EE;
    int f   = fe / EE;
    int c   = w * 32 + lane;
    float val = k[((size_t)(e * 9 + tap) * CINC + c) * FF + f];
    unsigned bits = __ballot_sync(0xFFFFFFFFu, val >= 0.f);
    if (lane == 0) g_kbits[idx] = bits;
#endif
}

// Prep 3 (sm_103a): beta image.
__global__ __launch_bounds__(256) void beta_kernel() {
#if HAS_TCG
    int pid = blockIdx.x * 256 + threadIdx.x;
    if (pid >= NPIX_OUT) return;
    int ow = pid % OW;
    int t  = pid / OW;
    int oh = t % OH;
    int b  = t / OH;
    float s = 0.f;
    #pragma unroll
    for (int dy = 0; dy < 3; dy++)
        #pragma unroll
        for (int dx = 0; dx < 3; dx++)
            s += g_S[(b * HH + oh + dy) * WW + (ow + dx)];
    g_beta[pid] = s * (1.0f / (float)DD);
#endif
}

// ---------------------------------------------------------------------------
// Main (sm_103a): PERSISTENT TS-mode implicit-GEMM conv, 148 CTAs.
// Jobs j in [0,14080): seg = j/110 (b=seg>>3, fs=seg&7), oh = j%110.
// A rows live in a 4-slot TMEM ring (cols 0..255, 64 cols each), written by a
// LOADER warpgroup (warps 8-11: LDG from g_xq -> STTM), bypassing SMEM.
// SMEM holds only B (3 x 24KB, SW128) + epilogue staging -> MMA SMEM traffic
// drops from 168KB/row to 72KB/row (the R14 L1=74% bottleneck).
// MMA warp 12: per row, 24 TS dispatches into D ping-pong (cols 256+p*96).
// Epilogue warps 0-7 in two groups by row parity. dx applied by lane shift.
// ---------------------------------------------------------------------------
__global__ __launch_bounds__(NTHREADS, 1) void abc_mma5_kernel(float* __restrict__ out) {
#if HAS_TCG
    extern __shared__ char smem[];
    const uint32_t sb = smem_u32(smem);
    const int tid = threadIdx.x;
    const int wid = tid >> 5;
    const int lane = tid & 31;

    const int jstart = (int)(((long long)blockIdx.x * NJOBS) / NCTA);
    const int jend   = (int)(((long long)(blockIdx.x + 1) * NJOBS) / NCTA);
    const int njobs  = jend - jstart;

    if (tid == 0) {
        MBARRIER_INIT(sb + SM_BBAR, 1);
        MBARRIER_INIT(sb + SM_BEMPTY, 1);
        #pragma unroll
        for (int i = 0; i < 4; i++) {
            MBARRIER_INIT(sb + SM_AFULL(i), 4);   // 4 loader warps arrive
            MBARRIER_INIT(sb + SM_AEMPTY(i), 1);  // MMA commit
        }
        #pragma unroll
        for (int i = 0; i < 2; i++) {
            MBARRIER_INIT(sb + SM_ACC(i), 1);
            MBARRIER_INIT(sb + SM_EPI(i), 4);
        }
    }
    if (wid == 12) { TCGEN05_ALLOC(sb + SM_TMEM, 512); TCGEN05_RELINQ(); }
    __syncthreads();
    uint32_t tbase;
    asm volatile("ld.shared.b32 %0, [%1];" : "=r"(tbase) : "r"(sb + SM_TMEM));

    // ---------------- A loader warpgroup (warps 8-11) + B producer ----------
    if (wid >= 8 && wid < 12) {
        const int wg_tid = tid - 256;             // 0..127 = M lane = pixel
        const int w  = (wg_tid < WW) ? wg_tid : (WW - 1);  // clamp pad lanes
        const int xw = w & 7;                     // SW128 granule XOR key
        const uint32_t warp_off = (uint32_t)(wg_tid >> 5) << 21;
        int aph[4] = {0, 0, 0, 0};
        int lp = 0;
        int seg_idx = 0;
        for (int j = jstart; j < jend; ) {
            int seg = j / OH;
            int b = seg >> 3, fs = seg & 7;
            int r0 = j % OH;
            int segend = (seg + 1) * OH; if (segend > jend) segend = jend;
            int nrows = (segend - j) + 2;
            // B tiles (warp 8 elect only)
            if (wid == 8 && elect_one()) {
                if (seg_idx > 0) MBARRIER_WAIT(sb + SM_BEMPTY, (seg_idx - 1) & 1);
                MBARRIER_EXPECT_TX(sb + SM_BBAR, 3 * BT);
                #pragma unroll
                for (int t = 0; t < 3; t++)
                    BULK_G2S(sb + SMEM_B + t * BT, g_w + (size_t)(fs * 3 + t) * BT, BT, sb + SM_BBAR);
            }
            // A rows -> TMEM ring
            for (int r = 0; r < nrows; r++) {
                int slot = lp & 3;
                if (lp >= 4) { MBARRIER_WAIT(sb + SM_AEMPTY(slot), aph[slot]); aph[slot] ^= 1; }
                const uint4* src = reinterpret_cast<const uint4*>(
                    g_xq + (size_t)(b * HH + r0 + r) * RB);
                uint32_t regs[64];
                #pragma unroll
                for (int cc = 0; cc < 2; cc++)
                    #pragma unroll
                    for (int g2 = 0; g2 < 8; g2++) {
                        uint4 vv = src[cc * 896 + w * 8 + (g2 ^ xw)];
                        regs[cc * 32 + g2 * 4 + 0] = vv.x;
                        regs[cc * 32 + g2 * 4 + 1] = vv.y;
                        regs[cc * 32 + g2 * 4 + 2] = vv.z;
                        regs[cc * 32 + g2 * 4 + 3] = vv.w;
                    }
                TCGEN05_ST_X64(tbase + TM_A + slot * 64 + warp_off, regs);
                TCGEN05_WAIT_ST();
                TCGEN05_FENCE_BEFORE();
                if (elect_one()) MBARRIER_ARRIVE(sb + SM_AFULL(slot));
                lp++;
            }
            seg_idx++;
            j = segend;
        }
    }

    // ---------------- MMA (warp 12) ----------------
    if (wid == 12) {
        // B K-step descriptor offsets (16B units): cc1 at +12288B = 768 units
        const uint32_t bkoff[8] = {0, 2, 4, 6, 768, 770, 772, 774};
        int fph[4] = {0, 0, 0, 0};
        int Lw = 0;                        // next loaded-row index to wait on
        int Lbase = 0;                     // loaded rows before current segment
        int jj = 0;                        // local job counter
        int seg_idx = 0;
        for (int j = jstart; j < jend; ) {
            int seg = j / OH;
            int segend = (seg + 1) * OH; if (segend > jend) segend = jend;
            int n = segend - j;
            MBARRIER_WAIT(sb + SM_BBAR, seg_idx & 1);
            for (int r = 0; r < n; r++, jj++) {
                while (Lw <= Lbase + r + 2) {
                    int s = Lw & 3;
                    MBARRIER_WAIT(sb + SM_AFULL(s), fph[s]); fph[s] ^= 1;
                    Lw++;
                }
                if (jj >= 2) MBARRIER_WAIT(sb + SM_EPI(jj & 1), ((jj >> 1) - 1) & 1);
                TCGEN05_FENCE_AFTER();
                if (elect_one()) {
                    int p = jj & 1;
                    uint32_t dacc = tbase + TM_D + p * 96;
                    #pragma unroll
                    for (int dy = 0; dy < 3; dy++) {
                        uint32_t atm = tbase + TM_A + ((Lbase + r + dy) & 3) * 64;
                        uint64_t bd = make_desc(sb + SMEM_B + dy * BT);
                        #pragma unroll
                        for (int k = 0; k < 8; k++)
                            mma_f16_ts(dacc, atm + k * 8, bd + bkoff[k], MMA_IDESC,
                                       !(dy == 0 && k == 0));
                    }
                    TCGEN05_COMMIT(sb + SM_AEMPTY((Lbase + r) & 3));
                    TCGEN05_COMMIT(sb + SM_ACC(p));
                }
            }
            // release the 2 trailing input rows + B buffer of this segment
            if (elect_one()) {
                TCGEN05_COMMIT(sb + SM_AEMPTY((Lbase + n) & 3));
                TCGEN05_COMMIT(sb + SM_AEMPTY((Lbase + n + 1) & 3));
                TCGEN05_COMMIT(sb + SM_BEMPTY);
            }
            Lbase += n + 2;
            seg_idx++;
            j = segend;
        }
    }

    // ---------------- epilogue (warps 0-7, two groups by row parity) --------
    if (wid < 8) {
        const int g  = wid >> 2;           // group: 0 = even jobs, 1 = odd jobs
        const int lw = wid & 3;            // warp within group
        float* sD1 = reinterpret_cast<float*>(smem + ST_D1);
        float* sD2 = reinterpret_cast<float*>(smem + ST_D2);
        for (int jj = g; jj < njobs; jj += 2) {
            int j = jstart + jj;
            int seg = j / OH;
            int b = seg >> 3, fs = seg & 7;
            int oh = j % OH;
            int p = jj & 1;                // == g
            int q = g * 2 + ((jj >> 1) & 1);   // staging buffer index (4 sets)
            MBARRIER_WAIT(sb + SM_ACC(p), (jj >> 1) & 1);
            TCGEN05_FENCE_AFTER();
            uint32_t r0[32], r1[32], r2[32];
            TCGEN05_LD_X32(r0, tbase + TM_D + p * 96);
            TCGEN05_LD_X32(r1, tbase + TM_D + p * 96 + 32);
            TCGEN05_LD_X32(r2, tbase + TM_D + p * 96 + 64);
            TCGEN05_WAIT_LD();
            TCGEN05_FENCE_BEFORE();
            if (elect_one()) MBARRIER_ARRIVE(sb + SM_EPI(p));  // free accumulator

            if (lw > 0 && lane < 2) {
                #pragma unroll
                for (int jr = 0; jr < 32; jr++) {
                    if (lane == 0) sD1[q * 128 + lw * 32 + jr] = __uint_as_float(r1[jr]);
                    sD2[q * 256 + (lw * 2 + lane) * 32 + jr] = __uint_as_float(r2[jr]);
                }
            }
            asm volatile("bar.sync %0, 128;" :: "r"(1 + g) : "memory");

            int ow = lw * 32 + lane;
            bool valid = (ow < OW);
            float beta = 0.f;
            int pid = 0;
            if (valid) {
                pid = (b * OH + oh) * OW + ow;
                beta = g_beta[pid];
            }
            float v[32];
            #pragma unroll
            for (int jr = 0; jr < 32; jr++) {
                float f0 = __uint_as_float(r0[jr]);
                float f1 = __uint_as_float(__shfl_down_sync(0xFFFFFFFFu, r1[jr], 1));
                float f2 = __uint_as_float(__shfl_down_sync(0xFFFFFFFFu, r2[jr], 2));
                if (lane == 31 && lw < 3) f1 = sD1[q * 128 + (lw + 1) * 32 + jr];
                if (lane >= 30 && lw < 3) f2 = sD2[q * 256 + ((lw + 1) * 2 + (lane - 30)) * 32 + jr];
                v[jr] = beta * (f0 + f1 + f2);
            }
            if (valid) {
                float* ob = out + (size_t)pid * FF + fs * 32;
                #pragma unroll
                for (int qq = 0; qq < 8; qq++)
                    *reinterpret_cast<float4*>(ob + qq * 4) =
                        make_float4(v[qq * 4], v[qq * 4 + 1], v[qq * 4 + 2], v[qq * 4 + 3]);
            }
        }
    }

    __syncthreads();
    if (tid == 0) {
        MBARRIER_INVAL(sb + SM_BBAR);
        MBARRIER_INVAL(sb + SM_BEMPTY);
        #pragma unroll
        for (int i = 0; i < 4; i++) { MBARRIER_INVAL(sb + SM_AFULL(i)); MBARRIER_INVAL(sb + SM_AEMPTY(i)); }
        #pragma unroll
        for (int i = 0; i < 2; i++) { MBARRIER_INVAL(sb + SM_ACC(i)); MBARRIER_INVAL(sb + SM_EPI(i)); }
    }
    if (wid == 12) TCGEN05_DEALLOC(tbase, 512);
#endif  // HAS_TCG
}

// ---------------------------------------------------------------------------
// Fallback main (non-103a passes): R1 popcount kernel.
// ---------------------------------------------------------------------------
__global__ __launch_bounds__(256) void abc_popc_kernel(
    const float* __restrict__ alphas, float* __restrict__ out) {
#if !HAS_TCG
    extern __shared__ unsigned skb[];
    float* sa = reinterpret_cast<float*>(skb + KWORDS);
    for (int i = threadIdx.x; i < KWORDS; i += blockDim.x) skb[i] = g_kbits[i];
    for (int i = threadIdx.x; i < EE * FF; i += blockDim.x) sa[i] = alphas[i];
    __syncthreads();

    const float inv_d = 1.0f / (float)DD;
    for (int pid = blockIdx.x * blockDim.x + threadIdx.x; pid < NPIX_OUT;
         pid += gridDim.x * blockDim.x) {
        int ow  = pid % OW;
        int tmp = pid / OW;
        int oh  = tmp % OH;
        int b   = tmp / OH;
        uint4 win[9];
        float ssum = 0.f;
        #pragma unroll
        for (int dy = 0; dy < 3; dy++)
            #pragma unroll
            for (int dx = 0; dx < 3; dx++) {
                int p = (b * HH + oh + dy) * WW + (ow + dx);
                win[dy * 3 + dx] = reinterpret_cast<const uint4*>(g_xbits)[p];
                ssum += g_S[p];
            }
        float beta = ssum * inv_d;
        size_t obase = (size_t)pid * FF;
        for (int f0 = 0; f0 < FF; f0 += 4) {
            float4 r;
            #pragma unroll
            for (int fi = 0; fi < 4; fi++) {
                int f = f0 + fi;
                const uint4* kb = reinterpret_cast<const uint4*>(skb + f * (EE * 9 * CWRD));
                int p0 = 0, p1 = 0, p2 = 0;
                #pragma unroll
                for (int t = 0; t < 9; t++) {
                    uint4 xv = win[t];
                    uint4 k0 = kb[t], k1 = kb[9 + t], k2 = kb[18 + t];
                    p0 += __popc(xv.x ^ k0.x) + __popc(xv.y ^ k0.y) + __popc(xv.z ^ k0.z) + __popc(xv.w ^ k0.w);
                    p1 += __popc(xv.x ^ k1.x) + __popc(xv.y ^ k1.y) + __popc(xv.z ^ k1.z) + __popc(xv.w ^ k1.w);
                    p2 += __popc(xv.x ^ k2.x) + __popc(xv.y ^ k2.y) + __popc(xv.z ^ k2.z) + __popc(xv.w ^ k2.w);
                }
                float val = sa[f] * (float)(DD - 2 * p0) + sa[FF + f] * (float)(DD - 2 * p1)
                          + sa[2 * FF + f] * (float)(DD - 2 * p2);
                (&r.x)[fi] = beta * val;
            }
            *reinterpret_cast<float4*>(out + obase + f0) = r;
        }
    }
#endif  // !HAS_TCG
}

// ---------------------------------------------------------------------------
extern "C" void kernel_launch(void* const* d_in, const int* in_sizes, int n_in,
                              void* d_out, int out_size) {
    const float* x = (const float*)d_in[0];
    const float* k = (const float*)d_in[1];
    const float* a = (const float*)d_in[2];
    float* out = (float*)d_out;

    // Deterministic per-device arch dispatch (attribute query; capture-safe).
    int dev = 0, major = 0, minor = 0;
    cudaGetDevice(&dev);
    cudaDeviceGetAttribute(&major, cudaDevAttrComputeCapabilityMajor, dev);
    cudaDeviceGetAttribute(&minor, cudaDevAttrComputeCapabilityMinor, dev);
    const bool tcg = (major == 10 && minor == 3);

    binarize_kernel<<<NPIX_IN / 8, 256>>>(x);
    if (tcg) {
        wpack_kernel<<<(9 * CINC * FF) / 256, 256>>>(k, a);
        beta_kernel<<<(NPIX_OUT + 255) / 256, 256>>>();
        cudaFuncSetAttribute(abc_mma5_kernel,
                             cudaFuncAttributeMaxDynamicSharedMemorySize, SMEM_TOT);
        abc_mma5_kernel<<<NCTA, NTHREADS, SMEM_TOT>>>(out);
    } else {
        kpack_kernel<<<KWORDS / 8, 256>>>(k);
        cudaFuncSetAttribute(abc_popc_kernel,
                             cudaFuncAttributeMaxDynamicSharedMemorySize, POPC_SMEM);
        abc_popc_kernel<<<296, 256, POPC_SMEM>>>(a, out);
    }
}